// round 3
// baseline (speedup 1.0000x reference)
#include <cuda_runtime.h>

#define NN 768
#define NF 128
#define MF 256
#define GF 256
#define ALPHA 0.01f
#define INV_CNT (1.0f / (NN * NF))

// ---------------- scratch (no allocations allowed) ----------------
__device__ __align__(16) float g_msg[NN * MF];    // nodes @ we
__device__ __align__(16) float g_ebar[NN * MF];   // sum_j leaky(b + msg*e)
__device__ __align__(16) float g_pre[NN * NF];    // pre-layernorm new_nodes
__device__ float g_stats[2];                      // sum, sumsq
__device__ float g_colsum[NF];                    // column sums of g_pre

__device__ __forceinline__ float leaky(float x) { return fmaxf(x, ALPHA * x); }

// ---- packed f32x2 helpers (Blackwell) ----
__device__ __forceinline__ unsigned long long dup2(float x) {
    unsigned long long r;
    asm("mov.b64 %0, {%1, %1};" : "=l"(r) : "f"(x));
    return r;
}
__device__ __forceinline__ float2 unpack2(unsigned long long v) {
    float2 r;
    asm("mov.b64 {%0, %1}, %2;" : "=f"(r.x), "=f"(r.y) : "l"(v));
    return r;
}
// acc2 += leaky( m2 * e2 + b2 )   (element-wise on packed f32 pairs)
__device__ __forceinline__ void pleaky(unsigned long long& acc,
                                       unsigned long long m2,
                                       unsigned long long e2,
                                       unsigned long long b2) {
    asm("{\n\t"
        ".reg .b64 t2, a2;\n\t"
        ".reg .f32 tl, th, al, ah;\n\t"
        "fma.rn.f32x2 t2, %1, %2, %3;\n\t"
        "mul.rn.f32x2 a2, t2, %4;\n\t"
        "mov.b64 {tl, th}, t2;\n\t"
        "mov.b64 {al, ah}, a2;\n\t"
        "max.f32 tl, tl, al;\n\t"
        "max.f32 th, th, ah;\n\t"
        "mov.b64 t2, {tl, th};\n\t"
        "add.rn.f32x2 %0, %0, t2;\n\t"
        "}"
        : "+l"(acc)
        : "l"(m2), "l"(e2), "l"(b2), "l"(0x3C23D70A3C23D70AULL)); // (0.01f,0.01f)
}

// ---------------- K1: msg = nodes @ we  (768x128 @ 128x256) ----------------
// 96 blocks x 256 threads; block = 8 rows x 256 cols. Also zeroes reducers.
__global__ void k1_msg(const float* __restrict__ nodes, const float* __restrict__ we) {
    __shared__ float ns[8][NF];
    const int tx = threadIdx.x;
    const int i0 = blockIdx.x * 8;

    if (blockIdx.x == 0) {
        if (tx < 2) g_stats[tx] = 0.0f;
        if (tx < NF) g_colsum[tx] = 0.0f;
    }

    for (int t = tx; t < 8 * NF; t += 256) {
        ns[t >> 7][t & 127] = nodes[i0 * NF + t];
    }
    __syncthreads();

    float acc[8];
#pragma unroll
    for (int r = 0; r < 8; r++) acc[r] = 0.0f;

    for (int c = 0; c < NF; c++) {
        const float w = we[c * MF + tx];
#pragma unroll
        for (int r = 0; r < 8; r++) acc[r] = fmaf(ns[r][c], w, acc[r]);
    }
#pragma unroll
    for (int r = 0; r < 8; r++) g_msg[(i0 + r) * MF + tx] = acc[r];
}

// ---------------- K2: ebar[i,k] = sum_j leaky(b[k] + msg[j,k]*edges[i,j]) --
// grid (96, 4), 64 threads. Block = 8 rows (i, packed in f32x2 pairs) x 64 k.
// 384 blocks, all resident; msg L2 traffic 75 MB; fma floor ~1.5 ops/elem.
#define K2_TI 8
#define K2_TJ 128
#define K2_PAD 10   // 8 rows + 2 pad floats; row stride 40B keeps 8B alignment
__global__ void __launch_bounds__(64) k2_ebar(const float* __restrict__ edges,
                                              const float* __restrict__ b) {
    __shared__ __align__(8) float es[K2_TJ][K2_PAD];  // transposed: es[j][row]
    const int tx = threadIdx.x;                 // k within quarter
    const int k  = blockIdx.y * 64 + tx;
    const int i0 = blockIdx.x * K2_TI;
    const unsigned long long b2 = dup2(b[k]);

    unsigned long long acc[4];
#pragma unroll
    for (int p = 0; p < 4; p++) acc[p] = 0ULL;  // (0.0f, 0.0f)

    for (int jt = 0; jt < NN; jt += K2_TJ) {
        // fill 8x128 edge tile, transposed so row-pairs are contiguous
#pragma unroll
        for (int t = tx; t < K2_TI * K2_TJ; t += 64) {
            const int r = t >> 7;
            const int j = t & 127;
            es[j][r] = edges[(i0 + r) * NN + jt + j];
        }
        __syncthreads();

#pragma unroll 4
        for (int j = 0; j < K2_TJ; j++) {
            const float m = __ldg(&g_msg[(jt + j) * MF + k]);
            const unsigned long long m2 = dup2(m);
            const unsigned long long* ep =
                reinterpret_cast<const unsigned long long*>(&es[j][0]);
            pleaky(acc[0], m2, ep[0], b2);
            pleaky(acc[1], m2, ep[1], b2);
            pleaky(acc[2], m2, ep[2], b2);
            pleaky(acc[3], m2, ep[3], b2);
        }
        __syncthreads();
    }
#pragma unroll
    for (int p = 0; p < 4; p++) {
        const float2 v = unpack2(acc[p]);
        g_ebar[(i0 + 2 * p)     * MF + k] = v.x;
        g_ebar[(i0 + 2 * p + 1) * MF + k] = v.y;
    }
}

// ---------------- K3: pre = leaky(ebar @ wv) + nodes; partial stats --------
// 192 blocks x 128 threads; block = 4 rows x 128 cols.
__global__ void k3_pre(const float* __restrict__ nodes, const float* __restrict__ wv) {
    __shared__ float eb[4][MF];
    __shared__ float red[128];
    const int tx = threadIdx.x;
    const int i0 = blockIdx.x * 4;

    for (int t = tx; t < 4 * MF; t += 128) {
        eb[t >> 8][t & 255] = g_ebar[i0 * MF + t];
    }
    __syncthreads();

    float acc[4];
#pragma unroll
    for (int r = 0; r < 4; r++) acc[r] = 0.0f;

    for (int c = 0; c < MF; c++) {
        const float w = wv[c * NF + tx];
#pragma unroll
        for (int r = 0; r < 4; r++) acc[r] = fmaf(eb[r][c], w, acc[r]);
    }

    float lsum = 0.0f, lss = 0.0f;
#pragma unroll
    for (int r = 0; r < 4; r++) {
        const float v = leaky(acc[r]) + nodes[(i0 + r) * NF + tx];
        g_pre[(i0 + r) * NF + tx] = v;
        lsum += v;
        lss = fmaf(v, v, lss);
    }
    atomicAdd(&g_colsum[tx], lsum);   // thread tx owns column tx

    // block-reduce sum and sumsq
    red[tx] = lsum;
    __syncthreads();
    for (int s = 64; s > 0; s >>= 1) {
        if (tx < s) red[tx] += red[tx + s];
        __syncthreads();
    }
    if (tx == 0) atomicAdd(&g_stats[0], red[0]);
    __syncthreads();
    red[tx] = lss;
    __syncthreads();
    for (int s = 64; s > 0; s >>= 1) {
        if (tx < s) red[tx] += red[tx + s];
        __syncthreads();
    }
    if (tx == 0) atomicAdd(&g_stats[1], red[0]);
}

// ---------------- K45: fused normalize + features -------------------------
// grid 104 x 256 threads. Blocks 0..95: normalize g_pre -> out_nodes (float4).
// Blocks 96..103: features — block fb computes 32 outputs, coalesced wu reads.
__global__ void k45(const float* __restrict__ features, const float* __restrict__ wu,
                    float4* __restrict__ out_nodes, float* __restrict__ out_feat) {
    const float mu = g_stats[0] * INV_CNT;
    const float var = g_stats[1] * INV_CNT - mu * mu;
    const float rs = rsqrtf(var + 1e-5f);
    const int bx = blockIdx.x;
    const int tx = threadIdx.x;

    if (bx < 96) {
        const int idx = bx * 256 + tx;
        const float4 v = reinterpret_cast<const float4*>(g_pre)[idx];
        float4 o;
        o.x = (v.x - mu) * rs;
        o.y = (v.y - mu) * rs;
        o.z = (v.z - mu) * rs;
        o.w = (v.w - mu) * rs;
        out_nodes[idx] = o;
    } else {
        __shared__ float gs[NF];
        if (tx < NF) gs[tx] = (g_colsum[tx] - (float)NN * mu) * rs;
        __syncthreads();
        if (tx < 32) {
            const int o = (bx - 96) * 32 + tx;
            float acc = 0.0f;
#pragma unroll 8
            for (int c = 0; c < NF; c++) acc = fmaf(gs[c], wu[c * GF + o], acc);
            out_feat[o] = leaky(acc) + features[o];
        }
    }
}

// ---------------- launch ---------------------------------------------------
extern "C" void kernel_launch(void* const* d_in, const int* in_sizes, int n_in,
                              void* d_out, int out_size) {
    (void)in_sizes; (void)n_in; (void)out_size;
    const float* nodes    = (const float*)d_in[0];
    const float* edges    = (const float*)d_in[1];
    const float* features = (const float*)d_in[2];
    const float* we       = (const float*)d_in[3];
    const float* b        = (const float*)d_in[4];
    const float* wv       = (const float*)d_in[5];
    const float* wu       = (const float*)d_in[6];

    float* out       = (float*)d_out;
    float* out_nodes = out;                       // [768*128]
    float* out_edges = out + NN * NF;             // [768*768]
    float* out_feat  = out + NN * NF + NN * NN;   // [256]

    cudaMemcpyAsync(out_edges, edges, (size_t)NN * NN * sizeof(float),
                    cudaMemcpyDeviceToDevice);

    k1_msg<<<96, 256>>>(nodes, we);
    dim3 g2(96, 4);
    k2_ebar<<<g2, 64>>>(edges, b);
    k3_pre<<<192, 128>>>(nodes, wv);
    k45<<<104, 256>>>(features, wu, (float4*)out_nodes, out_feat);
}

// round 5
// speedup vs baseline: 1.1552x; 1.1552x over previous
#include <cuda_runtime.h>

#define NN 768
#define NF 128
#define MF 256
#define GF 256
#define ALPHA 0.01f
#define INV_CNT (1.0f / (NN * NF))

// ---------------- scratch (no allocations allowed) ----------------
__device__ __align__(16) float g_msg[NN * MF];    // nodes @ we
__device__ __align__(16) float g_ebar[NN * MF];   // sum_j leaky(b + msg*e)
__device__ __align__(16) float g_pre[NN * NF];    // pre-layernorm new_nodes
__device__ float g_stats[2];                      // sum, sumsq
__device__ float g_colsum[NF];                    // column sums of g_pre

__device__ __forceinline__ float leaky(float x) { return fmaxf(x, ALPHA * x); }

// ---------------- K1: msg = nodes @ we  (768x128 @ 128x256) ----------------
// 96 blocks x 256 threads; block = 8 rows x 256 cols. Also zeroes reducers.
__global__ void k1_msg(const float* __restrict__ nodes, const float* __restrict__ we) {
    __shared__ float ns[8][NF];
    const int tx = threadIdx.x;
    const int i0 = blockIdx.x * 8;

    if (blockIdx.x == 0) {
        if (tx < 2) g_stats[tx] = 0.0f;
        if (tx < NF) g_colsum[tx] = 0.0f;
    }

    for (int t = tx; t < 8 * NF; t += 256) {
        ns[t >> 7][t & 127] = nodes[i0 * NF + t];
    }
    __syncthreads();

    float acc[8];
#pragma unroll
    for (int r = 0; r < 8; r++) acc[r] = 0.0f;

    for (int c = 0; c < NF; c++) {
        const float w = we[c * MF + tx];
#pragma unroll
        for (int r = 0; r < 8; r++) acc[r] = fmaf(ns[r][c], w, acc[r]);
    }
#pragma unroll
    for (int r = 0; r < 8; r++) g_msg[(i0 + r) * MF + tx] = acc[r];
}

// ---------------- K2: ebar[i,k] = sum_j leaky(b[k] + msg[j,k]*edges[i,j]) --
// Identity: leaky(t) = 0.505*t + 0.495*|t|  (exact for alpha=0.01)
//   => ebar = 0.505*sum(t) + 0.495*sum(|t|); 3 fma-pipe ops/element
//      (FFMA t; FADD acc_t; FADD acc_a with free |src| modifier).
// grid (192, 2), 128 threads. Block = 4 rows (i) x 128 cols (k-half).
// Edge tile stored transposed as float4 per j => 1 LDS.128 per j.
#define TI 4
#define TJ 128
__global__ void __launch_bounds__(128) k2_ebar(const float* __restrict__ edges,
                                               const float* __restrict__ b) {
    __shared__ float4 es[TJ];                  // es[j] = edges rows i0..i0+3 at col j
    const int tx = threadIdx.x;
    const int k  = blockIdx.y * 128 + tx;
    const int i0 = blockIdx.x * TI;
    const float bk = b[k];

    float acc_t[TI], acc_a[TI];
#pragma unroll
    for (int r = 0; r < TI; r++) { acc_t[r] = 0.0f; acc_a[r] = 0.0f; }

    for (int jt = 0; jt < NN; jt += TJ) {
        // fill transposed tile: es[j].{x,y,z,w} = edges[i0+{0,1,2,3}][jt+j]
        float* esf = reinterpret_cast<float*>(es);
#pragma unroll
        for (int t = tx; t < TI * TJ; t += 128) {
            const int r = t >> 7;              // row 0..3
            const int j = t & 127;
            esf[j * 4 + r] = edges[(i0 + r) * NN + jt + j];
        }
        __syncthreads();

#pragma unroll 4
        for (int j = 0; j < TJ; j++) {
            const float m = __ldg(&g_msg[(jt + j) * MF + k]);
            const float4 e4 = es[j];           // broadcast LDS.128
            float t0 = fmaf(m, e4.x, bk);
            float t1 = fmaf(m, e4.y, bk);
            float t2 = fmaf(m, e4.z, bk);
            float t3 = fmaf(m, e4.w, bk);
            acc_t[0] += t0;  acc_a[0] += fabsf(t0);
            acc_t[1] += t1;  acc_a[1] += fabsf(t1);
            acc_t[2] += t2;  acc_a[2] += fabsf(t2);
            acc_t[3] += t3;  acc_a[3] += fabsf(t3);
        }
        __syncthreads();
    }
#pragma unroll
    for (int r = 0; r < TI; r++) {
        g_ebar[(i0 + r) * MF + k] = fmaf(0.495f, acc_a[r], 0.505f * acc_t[r]);
    }
}

// ---------------- K3: pre = leaky(ebar @ wv) + nodes; partial stats --------
// 192 blocks x 128 threads; block = 4 rows x 128 cols.
__global__ void k3_pre(const float* __restrict__ nodes, const float* __restrict__ wv) {
    __shared__ float eb[4][MF];
    __shared__ float red[128];
    const int tx = threadIdx.x;
    const int i0 = blockIdx.x * 4;

    for (int t = tx; t < 4 * MF; t += 128) {
        eb[t >> 8][t & 255] = g_ebar[i0 * MF + t];
    }
    __syncthreads();

    float acc[4];
#pragma unroll
    for (int r = 0; r < 4; r++) acc[r] = 0.0f;

    for (int c = 0; c < MF; c++) {
        const float w = wv[c * NF + tx];
#pragma unroll
        for (int r = 0; r < 4; r++) acc[r] = fmaf(eb[r][c], w, acc[r]);
    }

    float lsum = 0.0f, lss = 0.0f;
#pragma unroll
    for (int r = 0; r < 4; r++) {
        const float v = leaky(acc[r]) + nodes[(i0 + r) * NF + tx];
        g_pre[(i0 + r) * NF + tx] = v;
        lsum += v;
        lss = fmaf(v, v, lss);
    }
    atomicAdd(&g_colsum[tx], lsum);   // thread tx owns column tx

    // block-reduce sum and sumsq
    red[tx] = lsum;
    __syncthreads();
    for (int s = 64; s > 0; s >>= 1) {
        if (tx < s) red[tx] += red[tx + s];
        __syncthreads();
    }
    if (tx == 0) atomicAdd(&g_stats[0], red[0]);
    __syncthreads();
    red[tx] = lss;
    __syncthreads();
    for (int s = 64; s > 0; s >>= 1) {
        if (tx < s) red[tx] += red[tx + s];
        __syncthreads();
    }
    if (tx == 0) atomicAdd(&g_stats[1], red[0]);
}

// ---------------- K45: fused normalize + features -------------------------
// grid 104 x 256 threads. Blocks 0..95: normalize g_pre -> out_nodes (float4).
// Blocks 96..103: features — block fb computes 32 outputs with ALL 256
// threads: 8 c-chunks x 32 outputs, partials reduced in smem.
__global__ void k45(const float* __restrict__ features, const float* __restrict__ wu,
                    float4* __restrict__ out_nodes, float* __restrict__ out_feat) {
    const float mu = g_stats[0] * INV_CNT;
    const float var = g_stats[1] * INV_CNT - mu * mu;
    const float rs = rsqrtf(var + 1e-5f);
    const int bx = blockIdx.x;
    const int tx = threadIdx.x;

    if (bx < 96) {
        const int idx = bx * 256 + tx;
        const float4 v = reinterpret_cast<const float4*>(g_pre)[idx];
        float4 o;
        o.x = (v.x - mu) * rs;
        o.y = (v.y - mu) * rs;
        o.z = (v.z - mu) * rs;
        o.w = (v.w - mu) * rs;
        out_nodes[idx] = o;
    } else {
        __shared__ float gs[NF];
        __shared__ float part[8][32];
        if (tx < NF) gs[tx] = (g_colsum[tx] - (float)NN * mu) * rs;
        __syncthreads();
        const int o  = (bx - 96) * 32 + (tx & 31);
        const int ch = tx >> 5;                 // 0..7, 16 c's each
        float acc = 0.0f;
#pragma unroll
        for (int cc = 0; cc < 16; cc++) {
            const int c = ch * 16 + cc;
            acc = fmaf(gs[c], wu[c * GF + o], acc);
        }
        part[ch][tx & 31] = acc;
        __syncthreads();
        if (tx < 32) {
            float s = 0.0f;
#pragma unroll
            for (int c2 = 0; c2 < 8; c2++) s += part[c2][tx];
            out_feat[(bx - 96) * 32 + tx] = leaky(s) + features[(bx - 96) * 32 + tx];
        }
    }
}

// ---------------- launch ---------------------------------------------------
extern "C" void kernel_launch(void* const* d_in, const int* in_sizes, int n_in,
                              void* d_out, int out_size) {
    (void)in_sizes; (void)n_in; (void)out_size;
    const float* nodes    = (const float*)d_in[0];
    const float* edges    = (const float*)d_in[1];
    const float* features = (const float*)d_in[2];
    const float* we       = (const float*)d_in[3];
    const float* b        = (const float*)d_in[4];
    const float* wv       = (const float*)d_in[5];
    const float* wu       = (const float*)d_in[6];

    float* out       = (float*)d_out;
    float* out_nodes = out;                       // [768*128]
    float* out_edges = out + NN * NF;             // [768*768]
    float* out_feat  = out + NN * NF + NN * NN;   // [256]

    cudaMemcpyAsync(out_edges, edges, (size_t)NN * NN * sizeof(float),
                    cudaMemcpyDeviceToDevice);

    k1_msg<<<96, 256>>>(nodes, we);
    dim3 g2(192, 2);
    k2_ebar<<<g2, 128>>>(edges, b);
    k3_pre<<<192, 128>>>(nodes, wv);
    k45<<<104, 256>>>(features, wu, (float4*)out_nodes, out_feat);
}

// round 6
// speedup vs baseline: 1.5290x; 1.3235x over previous
#include <cuda_runtime.h>

#define NN 768
#define NF 128
#define MF 256
#define GF 256
#define ALPHA 0.01f
#define INV_CNT (1.0f / (NN * NF))

// ---------------- scratch (no allocations allowed) ----------------
__device__ __align__(16) float g_msg[NN * MF];     // nodes @ we
__device__ __align__(16) float g_ebarp[2][NN * MF]; // partial ebar (j-halves)
__device__ __align__(16) float g_pre[NN * NF];     // pre-layernorm new_nodes
__device__ float g_stats[2];                       // sum, sumsq
__device__ float g_colsum[NF];                     // column sums of g_pre

__device__ __forceinline__ float leaky(float x) { return fmaxf(x, ALPHA * x); }

// ---------------- K1: msg = nodes @ we  (768x128 @ 128x256) ----------------
// 96 blocks x 256 threads; block = 8 rows x 256 cols. Also zeroes reducers.
__global__ void k1_msg(const float* __restrict__ nodes, const float* __restrict__ we) {
    __shared__ float ns[8][NF];
    const int tx = threadIdx.x;
    const int i0 = blockIdx.x * 8;

    if (blockIdx.x == 0) {
        if (tx < 2) g_stats[tx] = 0.0f;
        if (tx < NF) g_colsum[tx] = 0.0f;
    }

    for (int t = tx; t < 8 * NF; t += 256) {
        ns[t >> 7][t & 127] = nodes[i0 * NF + t];
    }
    __syncthreads();

    float acc[8];
#pragma unroll
    for (int r = 0; r < 8; r++) acc[r] = 0.0f;

    for (int c = 0; c < NF; c++) {
        const float w = we[c * MF + tx];
#pragma unroll
        for (int r = 0; r < 8; r++) acc[r] = fmaf(ns[r][c], w, acc[r]);
    }
#pragma unroll
    for (int r = 0; r < 8; r++) g_msg[(i0 + r) * MF + tx] = acc[r];
}

// ---------------- K2: partial ebar over a j-half ---------------------------
// leaky(t) = 0.505*t + 0.495*|t| (exact for alpha=0.01):
//   ebar = 0.505*sum(t) + 0.495*sum|t|  -> 3 fma-pipe ops/element.
// grid (96, 2, 2): bx = 8-row i-tile, by = k-half, bz = j-half (384 js).
// 384 blocks = 1 full wave, ~2.6 warps/SMSP. Each m-load feeds 24 fma ops
// (~51 rt-cycles) -> L2 latency self-hidden at unroll 4.
// by==0 blocks also stream the edge tile to out_edges (kills the D2D memcpy).
#define TI 8
#define TJ 128
#define JHALF 384
__global__ void __launch_bounds__(128) k2_ebar(const float* __restrict__ edges,
                                               const float* __restrict__ b,
                                               float* __restrict__ out_edges) {
    __shared__ __align__(16) float es[TJ][TI];   // transposed: es[j][row], 2x float4
    const int tx = threadIdx.x;
    const int k  = blockIdx.y * 128 + tx;
    const int i0 = blockIdx.x * TI;
    const int j0 = blockIdx.z * JHALF;
    const float bk = b[k];
    const bool wr_edges = (blockIdx.y == 0);

    float acc_t[TI], acc_a[TI];
#pragma unroll
    for (int r = 0; r < TI; r++) { acc_t[r] = 0.0f; acc_a[r] = 0.0f; }

    for (int jt = j0; jt < j0 + JHALF; jt += TJ) {
        // fill transposed tile: thread tx owns column j=tx, rows 0..7
#pragma unroll
        for (int r = 0; r < TI; r++) {
            const float v = edges[(i0 + r) * NN + jt + tx];
            es[tx][r] = v;
            if (wr_edges) out_edges[(i0 + r) * NN + jt + tx] = v;
        }
        __syncthreads();

#pragma unroll 4
        for (int j = 0; j < TJ; j++) {
            const float m = __ldg(&g_msg[(jt + j) * MF + k]);
            const float4 e0 = reinterpret_cast<const float4*>(es[j])[0];
            const float4 e1 = reinterpret_cast<const float4*>(es[j])[1];
            float t0 = fmaf(m, e0.x, bk);
            float t1 = fmaf(m, e0.y, bk);
            float t2 = fmaf(m, e0.z, bk);
            float t3 = fmaf(m, e0.w, bk);
            float t4 = fmaf(m, e1.x, bk);
            float t5 = fmaf(m, e1.y, bk);
            float t6 = fmaf(m, e1.z, bk);
            float t7 = fmaf(m, e1.w, bk);
            acc_t[0] += t0;  acc_a[0] += fabsf(t0);
            acc_t[1] += t1;  acc_a[1] += fabsf(t1);
            acc_t[2] += t2;  acc_a[2] += fabsf(t2);
            acc_t[3] += t3;  acc_a[3] += fabsf(t3);
            acc_t[4] += t4;  acc_a[4] += fabsf(t4);
            acc_t[5] += t5;  acc_a[5] += fabsf(t5);
            acc_t[6] += t6;  acc_a[6] += fabsf(t6);
            acc_t[7] += t7;  acc_a[7] += fabsf(t7);
        }
        __syncthreads();
    }
#pragma unroll
    for (int r = 0; r < TI; r++) {
        g_ebarp[blockIdx.z][(i0 + r) * MF + k] =
            fmaf(0.495f, acc_a[r], 0.505f * acc_t[r]);
    }
}

// ---------------- K3: pre = leaky((ebarA+ebarB) @ wv) + nodes; stats -------
// 192 blocks x 128 threads; block = 4 rows x 128 cols.
__global__ void k3_pre(const float* __restrict__ nodes, const float* __restrict__ wv) {
    __shared__ float eb[4][MF];
    __shared__ float red[128];
    const int tx = threadIdx.x;
    const int i0 = blockIdx.x * 4;

    for (int t = tx; t < 4 * MF; t += 128) {
        eb[t >> 8][t & 255] = g_ebarp[0][i0 * MF + t] + g_ebarp[1][i0 * MF + t];
    }
    __syncthreads();

    float acc[4];
#pragma unroll
    for (int r = 0; r < 4; r++) acc[r] = 0.0f;

    for (int c = 0; c < MF; c++) {
        const float w = wv[c * NF + tx];
#pragma unroll
        for (int r = 0; r < 4; r++) acc[r] = fmaf(eb[r][c], w, acc[r]);
    }

    float lsum = 0.0f, lss = 0.0f;
#pragma unroll
    for (int r = 0; r < 4; r++) {
        const float v = leaky(acc[r]) + nodes[(i0 + r) * NF + tx];
        g_pre[(i0 + r) * NF + tx] = v;
        lsum += v;
        lss = fmaf(v, v, lss);
    }
    atomicAdd(&g_colsum[tx], lsum);   // thread tx owns column tx

    // block-reduce sum and sumsq
    red[tx] = lsum;
    __syncthreads();
    for (int s = 64; s > 0; s >>= 1) {
        if (tx < s) red[tx] += red[tx + s];
        __syncthreads();
    }
    if (tx == 0) atomicAdd(&g_stats[0], red[0]);
    __syncthreads();
    red[tx] = lss;
    __syncthreads();
    for (int s = 64; s > 0; s >>= 1) {
        if (tx < s) red[tx] += red[tx + s];
        __syncthreads();
    }
    if (tx == 0) atomicAdd(&g_stats[1], red[0]);
}

// ---------------- K45: fused normalize + features -------------------------
// grid 104 x 256 threads. Blocks 0..95: normalize g_pre -> out_nodes (float4).
// Blocks 96..103: features, 256 threads each (8 c-chunks x 32 outputs).
__global__ void k45(const float* __restrict__ features, const float* __restrict__ wu,
                    float4* __restrict__ out_nodes, float* __restrict__ out_feat) {
    const float mu = g_stats[0] * INV_CNT;
    const float var = g_stats[1] * INV_CNT - mu * mu;
    const float rs = rsqrtf(var + 1e-5f);
    const int bx = blockIdx.x;
    const int tx = threadIdx.x;

    if (bx < 96) {
        const int idx = bx * 256 + tx;
        const float4 v = reinterpret_cast<const float4*>(g_pre)[idx];
        float4 o;
        o.x = (v.x - mu) * rs;
        o.y = (v.y - mu) * rs;
        o.z = (v.z - mu) * rs;
        o.w = (v.w - mu) * rs;
        out_nodes[idx] = o;
    } else {
        __shared__ float gs[NF];
        __shared__ float part[8][32];
        if (tx < NF) gs[tx] = (g_colsum[tx] - (float)NN * mu) * rs;
        __syncthreads();
        const int o  = (bx - 96) * 32 + (tx & 31);
        const int ch = tx >> 5;                 // 0..7, 16 c's each
        float acc = 0.0f;
#pragma unroll
        for (int cc = 0; cc < 16; cc++) {
            const int c = ch * 16 + cc;
            acc = fmaf(gs[c], wu[c * GF + o], acc);
        }
        part[ch][tx & 31] = acc;
        __syncthreads();
        if (tx < 32) {
            float s = 0.0f;
#pragma unroll
            for (int c2 = 0; c2 < 8; c2++) s += part[c2][tx];
            out_feat[(bx - 96) * 32 + tx] = leaky(s) + features[(bx - 96) * 32 + tx];
        }
    }
}

// ---------------- launch ---------------------------------------------------
extern "C" void kernel_launch(void* const* d_in, const int* in_sizes, int n_in,
                              void* d_out, int out_size) {
    (void)in_sizes; (void)n_in; (void)out_size;
    const float* nodes    = (const float*)d_in[0];
    const float* edges    = (const float*)d_in[1];
    const float* features = (const float*)d_in[2];
    const float* we       = (const float*)d_in[3];
    const float* b        = (const float*)d_in[4];
    const float* wv       = (const float*)d_in[5];
    const float* wu       = (const float*)d_in[6];

    float* out       = (float*)d_out;
    float* out_nodes = out;                       // [768*128]
    float* out_edges = out + NN * NF;             // [768*768]
    float* out_feat  = out + NN * NF + NN * NN;   // [256]

    k1_msg<<<96, 256>>>(nodes, we);
    dim3 g2(96, 2, 2);
    k2_ebar<<<g2, 128>>>(edges, b, out_edges);
    k3_pre<<<192, 128>>>(nodes, wv);
    k45<<<104, 256>>>(features, wu, (float4*)out_nodes, out_feat);
}

// round 7
// speedup vs baseline: 1.7319x; 1.1327x over previous
#include <cuda_runtime.h>

#define NN 768
#define NF 128
#define MF 256
#define GF 256
#define ALPHA 0.01f
#define INV_CNT (1.0f / (NN * NF))

// ---------------- scratch (no allocations allowed) ----------------
__device__ __align__(16) float g_msg[NN * MF];      // nodes @ we
__device__ __align__(16) float g_ebarp[2][NN * MF]; // partial ebar (j-halves)
__device__ __align__(16) float g_pre[NN * NF];      // pre-layernorm new_nodes
__device__ float g_stats[2];                        // sum, sumsq
__device__ float g_colsum[NF];                      // column sums of g_pre

__device__ __forceinline__ float leaky(float x) { return fmaxf(x, ALPHA * x); }

// ---------------- K1: msg = nodes @ we  (768x128 @ 128x256) ----------------
// 96 blocks x 256 threads; block = 8 rows x 256 cols. Also zeroes reducers.
__global__ void k1_msg(const float* __restrict__ nodes, const float* __restrict__ we) {
    __shared__ float ns[8][NF];
    const int tx = threadIdx.x;
    const int i0 = blockIdx.x * 8;

    if (blockIdx.x == 0) {
        if (tx < 2) g_stats[tx] = 0.0f;
        if (tx < NF) g_colsum[tx] = 0.0f;
    }

    for (int t = tx; t < 8 * NF; t += 256) {
        ns[t >> 7][t & 127] = nodes[i0 * NF + t];
    }
    __syncthreads();

    float acc[8];
#pragma unroll
    for (int r = 0; r < 8; r++) acc[r] = 0.0f;

    for (int c = 0; c < NF; c++) {
        const float w = we[c * MF + tx];
#pragma unroll
        for (int r = 0; r < 8; r++) acc[r] = fmaf(ns[r][c], w, acc[r]);
    }
#pragma unroll
    for (int r = 0; r < 8; r++) g_msg[(i0 + r) * MF + tx] = acc[r];
}

// ---------------- K2: partial ebar over a j-half ---------------------------
// leaky(t) = 0.505*t + 0.495*|t| (exact for alpha=0.01):
//   ebar = 0.505*sum(t) + 0.495*sum|t|  -> 3 fma-pipe ops/element.
// grid (96, 2, 2): bx = 8-row i-tile, by = k-half, bz = j-half (384 js).
// msg tile STAGED IN SMEM (bulk float4 loads, MLP=16) so the inner loop has
// no global-latency chain: per j just 3 LDS + 24 fma ops.
// by==0 blocks also stream the edge tile to out_edges (replaces D2D memcpy).
#define TI 8
#define TJ 64
#define JHALF 384
__global__ void __launch_bounds__(128) k2_ebar(const float* __restrict__ edges,
                                               const float* __restrict__ b,
                                               float* __restrict__ out_edges) {
    __shared__ __align__(16) float ms[TJ][128];  // 32KB msg tile [j][k-local]
    __shared__ __align__(16) float es[TJ][12];   // edge tile [j][row], pad->16B align
    const int tx = threadIdx.x;
    const int kbase = blockIdx.y * 128;
    const int k  = kbase + tx;
    const int i0 = blockIdx.x * TI;
    const int j0 = blockIdx.z * JHALF;
    const float bk = b[k];
    const bool wr_edges = (blockIdx.y == 0);
    const int jc = tx & 63;          // edge-fill column
    const int r0 = (tx >> 6) * 4;    // edge-fill row group (0 or 4)
    const int c4 = tx & 31;          // msg-fill float4 column
    const int jr = tx >> 5;          // msg-fill row offset 0..3

    float acc_t[TI], acc_a[TI];
#pragma unroll
    for (int r = 0; r < TI; r++) { acc_t[r] = 0.0f; acc_a[r] = 0.0f; }

    for (int jt = j0; jt < j0 + JHALF; jt += TJ) {
        // msg tile: 64 rows x 128 k as float4, 16 independent loads/thread
        const float4* msrc =
            reinterpret_cast<const float4*>(g_msg + (size_t)jt * MF + kbase);
#pragma unroll
        for (int p = 0; p < 16; p++) {
            const int j = p * 4 + jr;
            const float4 v = msrc[j * (MF / 4) + c4];
            *reinterpret_cast<float4*>(&ms[j][c4 * 4]) = v;
        }
        // edge tile: thread (jc, r0) loads 4 rows at its column (coalesced in jc)
#pragma unroll
        for (int rr = 0; rr < 4; rr++) {
            const int r = r0 + rr;
            const float v = edges[(size_t)(i0 + r) * NN + jt + jc];
            es[jc][r] = v;
            if (wr_edges) out_edges[(size_t)(i0 + r) * NN + jt + jc] = v;
        }
        __syncthreads();

#pragma unroll 4
        for (int j = 0; j < TJ; j++) {
            const float m = ms[j][tx];                                   // LDS, bank-clean
            const float4 e0 = *reinterpret_cast<const float4*>(&es[j][0]); // LDS.128 bcast
            const float4 e1 = *reinterpret_cast<const float4*>(&es[j][4]);
            float t0 = fmaf(m, e0.x, bk);
            float t1 = fmaf(m, e0.y, bk);
            float t2 = fmaf(m, e0.z, bk);
            float t3 = fmaf(m, e0.w, bk);
            float t4 = fmaf(m, e1.x, bk);
            float t5 = fmaf(m, e1.y, bk);
            float t6 = fmaf(m, e1.z, bk);
            float t7 = fmaf(m, e1.w, bk);
            acc_t[0] += t0;  acc_a[0] += fabsf(t0);
            acc_t[1] += t1;  acc_a[1] += fabsf(t1);
            acc_t[2] += t2;  acc_a[2] += fabsf(t2);
            acc_t[3] += t3;  acc_a[3] += fabsf(t3);
            acc_t[4] += t4;  acc_a[4] += fabsf(t4);
            acc_t[5] += t5;  acc_a[5] += fabsf(t5);
            acc_t[6] += t6;  acc_a[6] += fabsf(t6);
            acc_t[7] += t7;  acc_a[7] += fabsf(t7);
        }
        __syncthreads();
    }
#pragma unroll
    for (int r = 0; r < TI; r++) {
        g_ebarp[blockIdx.z][(i0 + r) * MF + k] =
            fmaf(0.495f, acc_a[r], 0.505f * acc_t[r]);
    }
}

// ---------------- K3: pre = leaky((ebarA+ebarB) @ wv) + nodes; stats -------
// 192 blocks x 128 threads; block = 4 rows x 128 cols.
__global__ void k3_pre(const float* __restrict__ nodes, const float* __restrict__ wv) {
    __shared__ float eb[4][MF];
    __shared__ float red[128];
    const int tx = threadIdx.x;
    const int i0 = blockIdx.x * 4;

    for (int t = tx; t < 4 * MF; t += 128) {
        eb[t >> 8][t & 255] = g_ebarp[0][i0 * MF + t] + g_ebarp[1][i0 * MF + t];
    }
    __syncthreads();

    float acc[4];
#pragma unroll
    for (int r = 0; r < 4; r++) acc[r] = 0.0f;

    for (int c = 0; c < MF; c++) {
        const float w = wv[c * NF + tx];
#pragma unroll
        for (int r = 0; r < 4; r++) acc[r] = fmaf(eb[r][c], w, acc[r]);
    }

    float lsum = 0.0f, lss = 0.0f;
#pragma unroll
    for (int r = 0; r < 4; r++) {
        const float v = leaky(acc[r]) + nodes[(i0 + r) * NF + tx];
        g_pre[(i0 + r) * NF + tx] = v;
        lsum += v;
        lss = fmaf(v, v, lss);
    }
    atomicAdd(&g_colsum[tx], lsum);   // thread tx owns column tx

    // block-reduce sum and sumsq
    red[tx] = lsum;
    __syncthreads();
    for (int s = 64; s > 0; s >>= 1) {
        if (tx < s) red[tx] += red[tx + s];
        __syncthreads();
    }
    if (tx == 0) atomicAdd(&g_stats[0], red[0]);
    __syncthreads();
    red[tx] = lss;
    __syncthreads();
    for (int s = 64; s > 0; s >>= 1) {
        if (tx < s) red[tx] += red[tx + s];
        __syncthreads();
    }
    if (tx == 0) atomicAdd(&g_stats[1], red[0]);
}

// ---------------- K45: fused normalize + features -------------------------
// grid 104 x 256 threads. Blocks 0..95: normalize g_pre -> out_nodes (float4).
// Blocks 96..103: features, 256 threads each (8 c-chunks x 32 outputs).
__global__ void k45(const float* __restrict__ features, const float* __restrict__ wu,
                    float4* __restrict__ out_nodes, float* __restrict__ out_feat) {
    const float mu = g_stats[0] * INV_CNT;
    const float var = g_stats[1] * INV_CNT - mu * mu;
    const float rs = rsqrtf(var + 1e-5f);
    const int bx = blockIdx.x;
    const int tx = threadIdx.x;

    if (bx < 96) {
        const int idx = bx * 256 + tx;
        const float4 v = reinterpret_cast<const float4*>(g_pre)[idx];
        float4 o;
        o.x = (v.x - mu) * rs;
        o.y = (v.y - mu) * rs;
        o.z = (v.z - mu) * rs;
        o.w = (v.w - mu) * rs;
        out_nodes[idx] = o;
    } else {
        __shared__ float gs[NF];
        __shared__ float part[8][32];
        if (tx < NF) gs[tx] = (g_colsum[tx] - (float)NN * mu) * rs;
        __syncthreads();
        const int o  = (bx - 96) * 32 + (tx & 31);
        const int ch = tx >> 5;                 // 0..7, 16 c's each
        float acc = 0.0f;
#pragma unroll
        for (int cc = 0; cc < 16; cc++) {
            const int c = ch * 16 + cc;
            acc = fmaf(gs[c], wu[c * GF + o], acc);
        }
        part[ch][tx & 31] = acc;
        __syncthreads();
        if (tx < 32) {
            float s = 0.0f;
#pragma unroll
            for (int c2 = 0; c2 < 8; c2++) s += part[c2][tx];
            out_feat[(bx - 96) * 32 + tx] = leaky(s) + features[(bx - 96) * 32 + tx];
        }
    }
}

// ---------------- launch ---------------------------------------------------
extern "C" void kernel_launch(void* const* d_in, const int* in_sizes, int n_in,
                              void* d_out, int out_size) {
    (void)in_sizes; (void)n_in; (void)out_size;
    const float* nodes    = (const float*)d_in[0];
    const float* edges    = (const float*)d_in[1];
    const float* features = (const float*)d_in[2];
    const float* we       = (const float*)d_in[3];
    const float* b        = (const float*)d_in[4];
    const float* wv       = (const float*)d_in[5];
    const float* wu       = (const float*)d_in[6];

    float* out       = (float*)d_out;
    float* out_nodes = out;                       // [768*128]
    float* out_edges = out + NN * NF;             // [768*768]
    float* out_feat  = out + NN * NF + NN * NN;   // [256]

    k1_msg<<<96, 256>>>(nodes, we);
    dim3 g2(96, 2, 2);
    k2_ebar<<<g2, 128>>>(edges, b, out_edges);
    k3_pre<<<192, 128>>>(nodes, wv);
    k45<<<104, 256>>>(features, wu, (float4*)out_nodes, out_feat);
}

// round 9
// speedup vs baseline: 1.7916x; 1.0345x over previous
#include <cuda_runtime.h>

#define NN 768
#define NF 128
#define MF 256
#define GF 256
#define ALPHA 0.01f
#define INV_CNT (1.0f / (NN * NF))

// ---------------- scratch (no allocations allowed) ----------------
__device__ __align__(16) float g_msg[NN * MF];      // nodes @ we
__device__ __align__(16) float g_ebarp[2][NN * MF]; // partial ebar (j-halves)
__device__ __align__(16) float g_pre[NN * NF];      // pre-layernorm new_nodes
__device__ float g_stats[2];                        // sum, sumsq
__device__ float g_colsum[NF];                      // column sums of g_pre

__device__ __forceinline__ float leaky(float x) { return fmaxf(x, ALPHA * x); }

// acc += t via FFMA with immediate multiplier (rt_SMSP=1 vs FADD rt=2). Exact.
#define ACC_IMM(a, t) asm("fma.rn.f32 %0, %1, 0f3F800000, %0;" : "+f"(a) : "f"(t))

// ---------------- K1: msg = nodes @ we  (768x128 @ 128x256) ----------------
// 96 blocks x 256 threads; block = 8 rows x 256 cols. Also zeroes reducers.
__global__ void k1_msg(const float* __restrict__ nodes, const float* __restrict__ we) {
    __shared__ float ns[8][NF];
    const int tx = threadIdx.x;
    const int i0 = blockIdx.x * 8;

    if (blockIdx.x == 0) {
        if (tx < 2) g_stats[tx] = 0.0f;
        if (tx < NF) g_colsum[tx] = 0.0f;
    }

    for (int t = tx; t < 8 * NF; t += 256) {
        ns[t >> 7][t & 127] = nodes[i0 * NF + t];
    }
    __syncthreads();

    float acc[8];
#pragma unroll
    for (int r = 0; r < 8; r++) acc[r] = 0.0f;

    for (int c = 0; c < NF; c++) {
        const float w = we[c * MF + tx];
#pragma unroll
        for (int r = 0; r < 8; r++) acc[r] = fmaf(ns[r][c], w, acc[r]);
    }
#pragma unroll
    for (int r = 0; r < 8; r++) g_msg[(i0 + r) * MF + tx] = acc[r];
}

// ---------------- K2: partial ebar over a j-half ---------------------------
// leaky(t) = 0.505*t + 0.495*|t| (exact for alpha=0.01).
// grid (96, 2, 2): bx = 8-row i-tile, by = k-half, bz = j-half.
// Double-buffered cp.async pipeline: next msg/edge tile streams into smem
// while the current one is consumed -> fill latency fully hidden.
// Inner loop per element: FFMA(t) rt2 + FADD|t| rt2 + FFMA-imm rt1 = 5 rt-cyc.
#define TI 8
#define TJ 32
#define JHALF 384
#define NT (JHALF / TJ)   // 12 tiles per half

__device__ __forceinline__ void k2_fill(float (*ms)[128], float (*es)[12],
                                        const float* __restrict__ edges,
                                        int jt, int i0, int kbase,
                                        int jr, int c4, int jc, int rg) {
    const float4* msrc = reinterpret_cast<const float4*>(g_msg + (size_t)jt * MF + kbase);
    const unsigned mdst = (unsigned)__cvta_generic_to_shared(&ms[0][0]);
#pragma unroll
    for (int p = 0; p < 8; p++) {
        const int j = p * 4 + jr;
        asm volatile("cp.async.cg.shared.global [%0], [%1], 16;"
                     :: "r"(mdst + (unsigned)((j * 128 + c4 * 4) * 4)),
                        "l"(msrc + (size_t)j * (MF / 4) + c4));
    }
    const unsigned edst = (unsigned)__cvta_generic_to_shared(&es[jc][0]);
#pragma unroll
    for (int rr = 0; rr < 2; rr++) {
        asm volatile("cp.async.ca.shared.global [%0], [%1], 4;"
                     :: "r"(edst + (unsigned)((rg + rr) * 4)),
                        "l"(edges + (size_t)(i0 + rg + rr) * NN + jt + jc));
    }
    asm volatile("cp.async.commit_group;" ::: "memory");
}

__global__ void __launch_bounds__(128) k2_ebar(const float* __restrict__ edges,
                                               const float* __restrict__ b) {
    __shared__ __align__(16) float ms[2][TJ][128];  // 32KB msg tiles
    __shared__ __align__(16) float es[2][TJ][12];   // 3KB edge tiles (padded rows)
    const int tx = threadIdx.x;
    const int kbase = blockIdx.y * 128;
    const int k  = kbase + tx;
    const int i0 = blockIdx.x * TI;
    const int j0 = blockIdx.z * JHALF;
    const float bk = b[k];
    const int c4 = tx & 31;          // msg-fill float4 column
    const int jr = tx >> 5;          // msg-fill row offset 0..3
    const int jc = tx & 31;          // edge-fill column 0..31
    const int rg = (tx >> 5) * 2;    // edge-fill row group (0,2,4,6)

    float acc_t[TI], acc_a[TI];
#pragma unroll
    for (int r = 0; r < TI; r++) { acc_t[r] = 0.0f; acc_a[r] = 0.0f; }

    k2_fill(ms[0], es[0], edges, j0, i0, kbase, jr, c4, jc, rg);

    for (int t = 0; t < NT; t++) {
        if (t + 1 < NT) {
            k2_fill(ms[(t + 1) & 1], es[(t + 1) & 1], edges,
                    j0 + (t + 1) * TJ, i0, kbase, jr, c4, jc, rg);
            asm volatile("cp.async.wait_group 1;" ::: "memory");
        } else {
            asm volatile("cp.async.wait_group 0;" ::: "memory");
        }
        __syncthreads();

        const float (*msb)[128] = ms[t & 1];
        const float (*esb)[12]  = es[t & 1];
#pragma unroll 4
        for (int j = 0; j < TJ; j++) {
            const float m = msb[j][tx];                                     // bank-clean LDS
            const float4 e0 = *reinterpret_cast<const float4*>(&esb[j][0]); // LDS.128 bcast
            const float4 e1 = *reinterpret_cast<const float4*>(&esb[j][4]);
            float t0 = fmaf(m, e0.x, bk);
            float t1 = fmaf(m, e0.y, bk);
            float t2 = fmaf(m, e0.z, bk);
            float t3 = fmaf(m, e0.w, bk);
            float t4 = fmaf(m, e1.x, bk);
            float t5 = fmaf(m, e1.y, bk);
            float t6 = fmaf(m, e1.z, bk);
            float t7 = fmaf(m, e1.w, bk);
            acc_a[0] += fabsf(t0);  ACC_IMM(acc_t[0], t0);
            acc_a[1] += fabsf(t1);  ACC_IMM(acc_t[1], t1);
            acc_a[2] += fabsf(t2);  ACC_IMM(acc_t[2], t2);
            acc_a[3] += fabsf(t3);  ACC_IMM(acc_t[3], t3);
            acc_a[4] += fabsf(t4);  ACC_IMM(acc_t[4], t4);
            acc_a[5] += fabsf(t5);  ACC_IMM(acc_t[5], t5);
            acc_a[6] += fabsf(t6);  ACC_IMM(acc_t[6], t6);
            acc_a[7] += fabsf(t7);  ACC_IMM(acc_t[7], t7);
        }
        __syncthreads();   // all warps done with buffer (t&1) before tile t+2 refills it
    }
#pragma unroll
    for (int r = 0; r < TI; r++) {
        g_ebarp[blockIdx.z][(i0 + r) * MF + k] =
            fmaf(0.495f, acc_a[r], 0.505f * acc_t[r]);
    }
}

// ---------------- K3: pre = leaky((ebarA+ebarB) @ wv) + nodes; stats -------
// 192 blocks x 128 threads; block = 4 rows x 128 cols.
__global__ void k3_pre(const float* __restrict__ nodes, const float* __restrict__ wv) {
    __shared__ float eb[4][MF];
    __shared__ float red[128];
    const int tx = threadIdx.x;
    const int i0 = blockIdx.x * 4;

    for (int t = tx; t < 4 * MF; t += 128) {
        eb[t >> 8][t & 255] = g_ebarp[0][i0 * MF + t] + g_ebarp[1][i0 * MF + t];
    }
    __syncthreads();

    float acc[4];
#pragma unroll
    for (int r = 0; r < 4; r++) acc[r] = 0.0f;

    for (int c = 0; c < MF; c++) {
        const float w = wv[c * NF + tx];
#pragma unroll
        for (int r = 0; r < 4; r++) acc[r] = fmaf(eb[r][c], w, acc[r]);
    }

    float lsum = 0.0f, lss = 0.0f;
#pragma unroll
    for (int r = 0; r < 4; r++) {
        const float v = leaky(acc[r]) + nodes[(i0 + r) * NF + tx];
        g_pre[(i0 + r) * NF + tx] = v;
        lsum += v;
        lss = fmaf(v, v, lss);
    }
    atomicAdd(&g_colsum[tx], lsum);   // thread tx owns column tx

    // block-reduce sum and sumsq
    red[tx] = lsum;
    __syncthreads();
    for (int s = 64; s > 0; s >>= 1) {
        if (tx < s) red[tx] += red[tx + s];
        __syncthreads();
    }
    if (tx == 0) atomicAdd(&g_stats[0], red[0]);
    __syncthreads();
    red[tx] = lss;
    __syncthreads();
    for (int s = 64; s > 0; s >>= 1) {
        if (tx < s) red[tx] += red[tx + s];
        __syncthreads();
    }
    if (tx == 0) atomicAdd(&g_stats[1], red[0]);
}

// ---------------- K45: fused normalize + features -------------------------
// grid 104 x 256 threads. Blocks 0..95: normalize g_pre -> out_nodes (float4).
// Blocks 96..103: features, 256 threads each (8 c-chunks x 32 outputs).
__global__ void k45(const float* __restrict__ features, const float* __restrict__ wu,
                    float4* __restrict__ out_nodes, float* __restrict__ out_feat) {
    const float mu = g_stats[0] * INV_CNT;
    const float var = g_stats[1] * INV_CNT - mu * mu;
    const float rs = rsqrtf(var + 1e-5f);
    const int bx = blockIdx.x;
    const int tx = threadIdx.x;

    if (bx < 96) {
        const int idx = bx * 256 + tx;
        const float4 v = reinterpret_cast<const float4*>(g_pre)[idx];
        float4 o;
        o.x = (v.x - mu) * rs;
        o.y = (v.y - mu) * rs;
        o.z = (v.z - mu) * rs;
        o.w = (v.w - mu) * rs;
        out_nodes[idx] = o;
    } else {
        __shared__ float gs[NF];
        __shared__ float part[8][32];
        if (tx < NF) gs[tx] = (g_colsum[tx] - (float)NN * mu) * rs;
        __syncthreads();
        const int o  = (bx - 96) * 32 + (tx & 31);
        const int ch = tx >> 5;                 // 0..7, 16 c's each
        float acc = 0.0f;
#pragma unroll
        for (int cc = 0; cc < 16; cc++) {
            const int c = ch * 16 + cc;
            acc = fmaf(gs[c], wu[c * GF + o], acc);
        }
        part[ch][tx & 31] = acc;
        __syncthreads();
        if (tx < 32) {
            float s = 0.0f;
#pragma unroll
            for (int c2 = 0; c2 < 8; c2++) s += part[c2][tx];
            out_feat[(bx - 96) * 32 + tx] = leaky(s) + features[(bx - 96) * 32 + tx];
        }
    }
}

// ---------------- launch ---------------------------------------------------
extern "C" void kernel_launch(void* const* d_in, const int* in_sizes, int n_in,
                              void* d_out, int out_size) {
    (void)in_sizes; (void)n_in; (void)out_size;
    const float* nodes    = (const float*)d_in[0];
    const float* edges    = (const float*)d_in[1];
    const float* features = (const float*)d_in[2];
    const float* we       = (const float*)d_in[3];
    const float* b        = (const float*)d_in[4];
    const float* wv       = (const float*)d_in[5];
    const float* wu       = (const float*)d_in[6];

    float* out       = (float*)d_out;
    float* out_nodes = out;                       // [768*128]
    float* out_edges = out + NN * NF;             // [768*768]
    float* out_feat  = out + NN * NF + NN * NN;   // [256]

    cudaMemcpyAsync(out_edges, edges, (size_t)NN * NN * sizeof(float),
                    cudaMemcpyDeviceToDevice);

    k1_msg<<<96, 256>>>(nodes, we);
    dim3 g2(96, 2, 2);
    k2_ebar<<<g2, 128>>>(edges, b);
    k3_pre<<<192, 128>>>(nodes, wv);
    k45<<<104, 256>>>(features, wu, (float4*)out_nodes, out_feat);
}

// round 11
// speedup vs baseline: 1.8936x; 1.0569x over previous
#include <cuda_runtime.h>

#define NN 768
#define NF 128
#define MF 256
#define GF 256
#define ALPHA 0.01f
#define INV_CNT (1.0f / (NN * NF))

// ---------------- scratch (no allocations allowed) ----------------
__device__ __align__(16) float g_msg[NN * MF];      // nodes @ we
__device__ __align__(16) float g_ebarp[3][NN * MF]; // partial ebar (j-thirds)
__device__ __align__(16) float g_pre[NN * NF];      // pre-layernorm new_nodes
__device__ float g_stats[2];                        // sum, sumsq
__device__ float g_colsum[NF];                      // column sums of g_pre

__device__ __forceinline__ float leaky(float x) { return fmaxf(x, ALPHA * x); }

// acc += t via FFMA with immediate multiplier (rt_SMSP=1 vs FADD rt=2). Exact.
#define ACC_IMM(a, t) asm("fma.rn.f32 %0, %1, 0f3F800000, %0;" : "+f"(a) : "f"(t))
// |t| on the ALU pipe (LOP3), freeing the fma pipe. Bit-exact fabsf.
__device__ __forceinline__ float fabs_alu(float x) {
    return __int_as_float(__float_as_int(x) & 0x7fffffff);
}

// ---------------- K1: msg = nodes @ we  (768x128 @ 128x256) ----------------
// 96 blocks x 256 threads; block = 8 rows x 256 cols. Also zeroes reducers.
__global__ void k1_msg(const float* __restrict__ nodes, const float* __restrict__ we) {
    __shared__ float ns[8][NF];
    const int tx = threadIdx.x;
    const int i0 = blockIdx.x * 8;

    if (blockIdx.x == 0) {
        if (tx < 2) g_stats[tx] = 0.0f;
        if (tx < NF) g_colsum[tx] = 0.0f;
    }

    for (int t = tx; t < 8 * NF; t += 256) {
        ns[t >> 7][t & 127] = nodes[i0 * NF + t];
    }
    __syncthreads();

    float acc[8];
#pragma unroll
    for (int r = 0; r < 8; r++) acc[r] = 0.0f;

    for (int c = 0; c < NF; c++) {
        const float w = we[c * MF + tx];
#pragma unroll
        for (int r = 0; r < 8; r++) acc[r] = fmaf(ns[r][c], w, acc[r]);
    }
#pragma unroll
    for (int r = 0; r < 8; r++) g_msg[(i0 + r) * MF + tx] = acc[r];
}

// ---------------- K2: partial ebar over a j-third --------------------------
// leaky(t) = 0.505*t + 0.495*|t| (exact for alpha=0.01).
// grid (96, 2, 3): bx = 8-row i-tile, by = k-half, bz = j-third (256 js).
// 576 blocks, all resident (~3.9 warps/SMSP). Double-buffered cp.async.
// Per element: FFMA(t) rt2 [fma] + LOP3 |t| rt2 [alu] + 2x FFMA-imm rt1 [fma]
//   -> fma-pipe 4 rt-cyc, alu 2 (parallel), issue 4.375.
#define TI 8
#define TJ 32
#define JT 256
#define NT (JT / TJ)   // 8 tiles per third

__device__ __forceinline__ void k2_fill(float (*ms)[128], float (*es)[12],
                                        const float* __restrict__ edges,
                                        int jt, int i0, int kbase,
                                        int jr, int c4, int jc, int rg) {
    const float4* msrc = reinterpret_cast<const float4*>(g_msg + (size_t)jt * MF + kbase);
    const unsigned mdst = (unsigned)__cvta_generic_to_shared(&ms[0][0]);
#pragma unroll
    for (int p = 0; p < 8; p++) {
        const int j = p * 4 + jr;
        asm volatile("cp.async.cg.shared.global [%0], [%1], 16;"
                     :: "r"(mdst + (unsigned)((j * 128 + c4 * 4) * 4)),
                        "l"(msrc + (size_t)j * (MF / 4) + c4));
    }
    const unsigned edst = (unsigned)__cvta_generic_to_shared(&es[jc][0]);
#pragma unroll
    for (int rr = 0; rr < 2; rr++) {
        asm volatile("cp.async.ca.shared.global [%0], [%1], 4;"
                     :: "r"(edst + (unsigned)((rg + rr) * 4)),
                        "l"(edges + (size_t)(i0 + rg + rr) * NN + jt + jc));
    }
    asm volatile("cp.async.commit_group;" ::: "memory");
}

__global__ void __launch_bounds__(128) k2_ebar(const float* __restrict__ edges,
                                               const float* __restrict__ b) {
    __shared__ __align__(16) float ms[2][TJ][128];  // 2x16KB msg tiles
    __shared__ __align__(16) float es[2][TJ][12];   // edge tiles (padded rows)
    const int tx = threadIdx.x;
    const int kbase = blockIdx.y * 128;
    const int k  = kbase + tx;
    const int i0 = blockIdx.x * TI;
    const int j0 = blockIdx.z * JT;
    const float bk = b[k];
    const int c4 = tx & 31;          // msg-fill float4 column
    const int jr = tx >> 5;          // msg-fill row offset 0..3
    const int jc = tx & 31;          // edge-fill column 0..31
    const int rg = (tx >> 5) * 2;    // edge-fill row group (0,2,4,6)

    float acc_t[TI], acc_a[TI];
#pragma unroll
    for (int r = 0; r < TI; r++) { acc_t[r] = 0.0f; acc_a[r] = 0.0f; }

    k2_fill(ms[0], es[0], edges, j0, i0, kbase, jr, c4, jc, rg);

    for (int t = 0; t < NT; t++) {
        if (t + 1 < NT) {
            k2_fill(ms[(t + 1) & 1], es[(t + 1) & 1], edges,
                    j0 + (t + 1) * TJ, i0, kbase, jr, c4, jc, rg);
            asm volatile("cp.async.wait_group 1;" ::: "memory");
        } else {
            asm volatile("cp.async.wait_group 0;" ::: "memory");
        }
        __syncthreads();

        const float (*msb)[128] = ms[t & 1];
        const float (*esb)[12]  = es[t & 1];
#pragma unroll 4
        for (int j = 0; j < TJ; j++) {
            const float m = msb[j][tx];                                     // bank-clean LDS
            const float4 e0 = *reinterpret_cast<const float4*>(&esb[j][0]); // LDS.128 bcast
            const float4 e1 = *reinterpret_cast<const float4*>(&esb[j][4]);
            float t0 = fmaf(m, e0.x, bk);
            float t1 = fmaf(m, e0.y, bk);
            float t2 = fmaf(m, e0.z, bk);
            float t3 = fmaf(m, e0.w, bk);
            float t4 = fmaf(m, e1.x, bk);
            float t5 = fmaf(m, e1.y, bk);
            float t6 = fmaf(m, e1.z, bk);
            float t7 = fmaf(m, e1.w, bk);
            ACC_IMM(acc_t[0], t0);  ACC_IMM(acc_a[0], fabs_alu(t0));
            ACC_IMM(acc_t[1], t1);  ACC_IMM(acc_a[1], fabs_alu(t1));
            ACC_IMM(acc_t[2], t2);  ACC_IMM(acc_a[2], fabs_alu(t2));
            ACC_IMM(acc_t[3], t3);  ACC_IMM(acc_a[3], fabs_alu(t3));
            ACC_IMM(acc_t[4], t4);  ACC_IMM(acc_a[4], fabs_alu(t4));
            ACC_IMM(acc_t[5], t5);  ACC_IMM(acc_a[5], fabs_alu(t5));
            ACC_IMM(acc_t[6], t6);  ACC_IMM(acc_a[6], fabs_alu(t6));
            ACC_IMM(acc_t[7], t7);  ACC_IMM(acc_a[7], fabs_alu(t7));
        }
        __syncthreads();   // all warps done with buffer (t&1) before tile t+2 refills it
    }
#pragma unroll
    for (int r = 0; r < TI; r++) {
        g_ebarp[blockIdx.z][(i0 + r) * MF + k] =
            fmaf(0.495f, acc_a[r], 0.505f * acc_t[r]);
    }
}

// ---------------- K3: pre = leaky((sum of ebar partials) @ wv) + nodes -----
// 192 blocks x 128 threads; block = 4 rows x 128 cols.
__global__ void k3_pre(const float* __restrict__ nodes, const float* __restrict__ wv) {
    __shared__ float eb[4][MF];
    __shared__ float red[128];
    const int tx = threadIdx.x;
    const int i0 = blockIdx.x * 4;

    for (int t = tx; t < 4 * MF; t += 128) {
        eb[t >> 8][t & 255] = g_ebarp[0][i0 * MF + t] + g_ebarp[1][i0 * MF + t]
                            + g_ebarp[2][i0 * MF + t];
    }
    __syncthreads();

    float acc[4];
#pragma unroll
    for (int r = 0; r < 4; r++) acc[r] = 0.0f;

    for (int c = 0; c < MF; c++) {
        const float w = wv[c * NF + tx];
#pragma unroll
        for (int r = 0; r < 4; r++) acc[r] = fmaf(eb[r][c], w, acc[r]);
    }

    float lsum = 0.0f, lss = 0.0f;
#pragma unroll
    for (int r = 0; r < 4; r++) {
        const float v = leaky(acc[r]) + nodes[(i0 + r) * NF + tx];
        g_pre[(i0 + r) * NF + tx] = v;
        lsum += v;
        lss = fmaf(v, v, lss);
    }
    atomicAdd(&g_colsum[tx], lsum);   // thread tx owns column tx

    // block-reduce sum and sumsq
    red[tx] = lsum;
    __syncthreads();
    for (int s = 64; s > 0; s >>= 1) {
        if (tx < s) red[tx] += red[tx + s];
        __syncthreads();
    }
    if (tx == 0) atomicAdd(&g_stats[0], red[0]);
    __syncthreads();
    red[tx] = lss;
    __syncthreads();
    for (int s = 64; s > 0; s >>= 1) {
        if (tx < s) red[tx] += red[tx + s];
        __syncthreads();
    }
    if (tx == 0) atomicAdd(&g_stats[1], red[0]);
}

// ---------------- K45: fused normalize + features -------------------------
// grid 104 x 256 threads. Blocks 0..95: normalize g_pre -> out_nodes (float4).
// Blocks 96..103: features, 256 threads each (8 c-chunks x 32 outputs).
__global__ void k45(const float* __restrict__ features, const float* __restrict__ wu,
                    float4* __restrict__ out_nodes, float* __restrict__ out_feat) {
    const float mu = g_stats[0] * INV_CNT;
    const float var = g_stats[1] * INV_CNT - mu * mu;
    const float rs = rsqrtf(var + 1e-5f);
    const int bx = blockIdx.x;
    const int tx = threadIdx.x;

    if (bx < 96) {
        const int idx = bx * 256 + tx;
        const float4 v = reinterpret_cast<const float4*>(g_pre)[idx];
        float4 o;
        o.x = (v.x - mu) * rs;
        o.y = (v.y - mu) * rs;
        o.z = (v.z - mu) * rs;
        o.w = (v.w - mu) * rs;
        out_nodes[idx] = o;
    } else {
        __shared__ float gs[NF];
        __shared__ float part[8][32];
        if (tx < NF) gs[tx] = (g_colsum[tx] - (float)NN * mu) * rs;
        __syncthreads();
        const int o  = (bx - 96) * 32 + (tx & 31);
        const int ch = tx >> 5;                 // 0..7, 16 c's each
        float acc = 0.0f;
#pragma unroll
        for (int cc = 0; cc < 16; cc++) {
            const int c = ch * 16 + cc;
            acc = fmaf(gs[c], wu[c * GF + o], acc);
        }
        part[ch][tx & 31] = acc;
        __syncthreads();
        if (tx < 32) {
            float s = 0.0f;
#pragma unroll
            for (int c2 = 0; c2 < 8; c2++) s += part[c2][tx];
            out_feat[(bx - 96) * 32 + tx] = leaky(s) + features[(bx - 96) * 32 + tx];
        }
    }
}

// ---------------- launch ---------------------------------------------------
extern "C" void kernel_launch(void* const* d_in, const int* in_sizes, int n_in,
                              void* d_out, int out_size) {
    (void)in_sizes; (void)n_in; (void)out_size;
    const float* nodes    = (const float*)d_in[0];
    const float* edges    = (const float*)d_in[1];
    const float* features = (const float*)d_in[2];
    const float* we       = (const float*)d_in[3];
    const float* b        = (const float*)d_in[4];
    const float* wv       = (const float*)d_in[5];
    const float* wu       = (const float*)d_in[6];

    float* out       = (float*)d_out;
    float* out_nodes = out;                       // [768*128]
    float* out_edges = out + NN * NF;             // [768*768]
    float* out_feat  = out + NN * NF + NN * NN;   // [256]

    cudaMemcpyAsync(out_edges, edges, (size_t)NN * NN * sizeof(float),
                    cudaMemcpyDeviceToDevice);

    k1_msg<<<96, 256>>>(nodes, we);
    dim3 g2(96, 2, 3);
    k2_ebar<<<g2, 128>>>(edges, b);
    k3_pre<<<192, 128>>>(nodes, wv);
    k45<<<104, 256>>>(features, wu, (float4*)out_nodes, out_feat);
}